// round 3
// baseline (speedup 1.0000x reference)
#include <cuda_runtime.h>
#include <math.h>

typedef unsigned long long u64;

// ---------- packed f32x2 helpers (FFMA2 is PTX-only on sm_103a) ----------
__device__ __forceinline__ u64 dup2(float v){
    u64 r; asm("mov.b64 %0, {%1, %1};" : "=l"(r) : "f"(v)); return r;
}
__device__ __forceinline__ u64 pk2(float lo, float hi){
    u64 r; asm("mov.b64 %0, {%1, %2};" : "=l"(r) : "f"(lo), "f"(hi)); return r;
}
__device__ __forceinline__ void upk2(u64 a, float &lo, float &hi){
    asm("mov.b64 {%0, %1}, %2;" : "=f"(lo), "=f"(hi) : "l"(a));
}
__device__ __forceinline__ u64 fma2(u64 a, u64 b, u64 c){
    u64 d; asm("fma.rn.f32x2 %0, %1, %2, %3;" : "=l"(d) : "l"(a), "l"(b), "l"(c)); return d;
}
__device__ __forceinline__ u64 lds2(const float* p){ return *reinterpret_cast<const u64*>(p); }

union V4 { uint4 q; u64 d[2]; };

// ---------- adjacency prologue ----------
__device__ float g_adj[576];

// edge_index may arrive as int32 (harness-narrowed) or int64. Detect at runtime:
// for int64 little-endian values in [0,24), every odd 32-bit word of the first
// 192 words is 0. For int32, odd words are random node ids.
__global__ void build_adj_kernel(const int* __restrict__ ei_raw){
    __shared__ float sdeg[24];
    __shared__ float sdinv[24];
    __shared__ float sA[576];
    __shared__ int ssrc[96], sdst[96];
    __shared__ int is64;
    int t = threadIdx.x;

    if (t == 0){
        int z = 1;
        #pragma unroll 1
        for (int i = 1; i < 192; i += 2)
            if (ei_raw[i] != 0){ z = 0; break; }
        is64 = z;
    }
    if (t < 24) sdeg[t] = 1.0f;          // self-loop
    if (t < 576) sA[t] = 0.0f;
    __syncthreads();

    if (t < 96){
        int s, d;
        if (is64){
            const long long* e = reinterpret_cast<const long long*>(ei_raw);
            s = (int)e[t]; d = (int)e[96 + t];
        } else {
            s = ei_raw[t]; d = ei_raw[96 + t];
        }
        s = min(max(s, 0), 23);
        d = min(max(d, 0), 23);
        ssrc[t] = s; sdst[t] = d;
        atomicAdd(&sdeg[d], 1.0f);
    }
    __syncthreads();
    if (t < 24) sdinv[t] = 1.0f / sqrtf(sdeg[t]);
    __syncthreads();
    if (t < 96){
        int s = ssrc[t], d = sdst[t];
        atomicAdd(&sA[d*24 + s], sdinv[s]*sdinv[d]);   // duplicate edges accumulate
    }
    if (t < 24) atomicAdd(&sA[t*24 + t], sdinv[t]*sdinv[t]);
    __syncthreads();
    if (t < 576) g_adj[t] = sA[t];
}

// ---------- fused GCN + FC kernel ----------
#define NT 768
#define TB 32

// shared-memory float offsets
constexpr int SM_H   = 0;        // 32*24*32 = 24576 floats
constexpr int SM_WT  = 24576;    // 64*128  = 8192 floats (fcw1 tile; later overlaid by sfc1 32*129)
constexpr int SM_A   = 32768;    // 24*25   = 600
constexpr int SM_W   = 33368;    // 1012
constexpr int SM_B   = 34380;    // 88
constexpr int SM_FB1 = 34468;    // 128
constexpr int SM_FW2 = 34596;    // 256
constexpr int SM_FB2 = 34852;    // 2
constexpr int SMEM_FLOATS = 34856;
constexpr int SMEM_BYTES  = SMEM_FLOATS * 4;   // 139424 B

template<int FIN, int FOUT, bool STORE>
__device__ __forceinline__ void gcn_layer(float* h, const float* sWl, const float* sBl,
                                          const float* sArow, const float* smemHb, float* myrow)
{
    constexpr int KP = FOUT / 2;
    // ---- hw = h @ W (per-thread, W broadcast from shared) ----
    {
        u64 acc[KP];
        #pragma unroll
        for (int k = 0; k < KP; k++) acc[k] = 0ull;
        #pragma unroll
        for (int fi = 0; fi < FIN; fi++){
            u64 d = dup2(h[fi]);
            #pragma unroll
            for (int k = 0; k < KP; k += 2){
                V4 wv; wv.q = *reinterpret_cast<const uint4*>(sWl + fi*FOUT + 2*k);
                acc[k]   = fma2(d, wv.d[0], acc[k]);
                acc[k+1] = fma2(d, wv.d[1], acc[k+1]);
            }
        }
        #pragma unroll
        for (int k = 0; k < KP; k += 2){
            V4 o; o.d[0] = acc[k]; o.d[1] = acc[k+1];
            *reinterpret_cast<uint4*>(myrow + 2*k) = o.q;
        }
    }
    __syncthreads();
    // ---- aggregate: out = A[node,:] @ hw + bias ----
    u64 acc2[KP];
    #pragma unroll
    for (int k = 0; k < KP; k++) acc2[k] = lds2(sBl + 2*k);
    #pragma unroll 4
    for (int j = 0; j < 24; j++){
        u64 a2 = dup2(sArow[j]);
        const float* row = smemHb + j*32;
        #pragma unroll
        for (int k = 0; k < KP; k += 2){
            V4 v; v.q = *reinterpret_cast<const uint4*>(row + 2*k);
            acc2[k]   = fma2(a2, v.d[0], acc2[k]);
            acc2[k+1] = fma2(a2, v.d[1], acc2[k+1]);
        }
    }
    __syncthreads();
    // ---- relu ----
    if (STORE){
        #pragma unroll
        for (int k = 0; k < KP; k += 2){
            float a,b,c,d;
            upk2(acc2[k], a, b); upk2(acc2[k+1], c, d);
            V4 o;
            o.d[0] = pk2(fmaxf(a,0.f), fmaxf(b,0.f));
            o.d[1] = pk2(fmaxf(c,0.f), fmaxf(d,0.f));
            *reinterpret_cast<uint4*>(myrow + 2*k) = o.q;
        }
    } else {
        #pragma unroll
        for (int k = 0; k < KP; k++){
            float lo, hi; upk2(acc2[k], lo, hi);
            h[2*k]   = fmaxf(lo, 0.f);
            h[2*k+1] = fmaxf(hi, 0.f);
        }
    }
}

__global__ __launch_bounds__(NT, 1)
void gcn_fused_kernel(const float* __restrict__ x,
                      const float* __restrict__ W1, const float* __restrict__ b1,
                      const float* __restrict__ W2, const float* __restrict__ b2,
                      const float* __restrict__ W3, const float* __restrict__ b3,
                      const float* __restrict__ W4, const float* __restrict__ b4,
                      const float* __restrict__ W5, const float* __restrict__ b5,
                      const float* __restrict__ W6, const float* __restrict__ b6,
                      const float* __restrict__ W7, const float* __restrict__ b7,
                      const float* __restrict__ fcw1, const float* __restrict__ fcb1,
                      const float* __restrict__ fcw2, const float* __restrict__ fcb2,
                      float* __restrict__ out)
{
    extern __shared__ float sm[];
    float* smemH  = sm + SM_H;
    float* sWtile = sm + SM_WT;
    float* sfc1   = sm + SM_WT;    // overlay (32*129 <= 8192)
    float* sA     = sm + SM_A;
    float* sW     = sm + SM_W;
    float* sB     = sm + SM_B;
    float* sFcb1  = sm + SM_FB1;
    float* sFcw2  = sm + SM_FW2;
    float* sFcb2  = sm + SM_FB2;

    const int t = threadIdx.x;

    // ---- stage constants into shared ----
    if (t < 576) sA[(t/24)*25 + (t%24)] = g_adj[t];   // padded rows -> conflict-free A reads
    if (t < 4)   sW[0   + t] = W1[t];
    if (t < 16)  sW[4   + t] = W2[t];
    if (t < 32)  sW[20  + t] = W3[t];
    if (t < 64)  sW[52  + t] = W4[t];
    if (t < 128) sW[116 + t] = W5[t];
    if (t < 256) sW[244 + t] = W6[t];
    if (t < 512) sW[500 + t] = W7[t];
    if (t < 4)   sB[0  + t] = b1[t];
    if (t < 4)   sB[4  + t] = b2[t];
    if (t < 8)   sB[8  + t] = b3[t];
    if (t < 8)   sB[16 + t] = b4[t];
    if (t < 16)  sB[24 + t] = b5[t];
    if (t < 16)  sB[40 + t] = b6[t];
    if (t < 32)  sB[56 + t] = b7[t];
    if (t < 128) sFcb1[t] = fcb1[t];
    if (t < 256) sFcw2[t] = fcw2[t];
    if (t < 2)   sFcb2[t] = fcb2[t];

    // ---- GCN phase: thread = (b_local, node) ----
    const int b_local = t / 24;
    const int node    = t % 24;
    float* smemHb = smemH + b_local * 768;      // [24][32]
    float* myrow  = smemHb + node * 32;
    const float* sArow = sA + node * 25;

    float h[16];
    h[0] = x[blockIdx.x * 768 + t];             // x layout [B,24,1] -> coalesced
    __syncthreads();

    gcn_layer< 1,  4, false>(h, sW + 0,   sB + 0,  sArow, smemHb, myrow);
    gcn_layer< 4,  4, false>(h, sW + 4,   sB + 4,  sArow, smemHb, myrow);
    gcn_layer< 4,  8, false>(h, sW + 20,  sB + 8,  sArow, smemHb, myrow);
    gcn_layer< 8,  8, false>(h, sW + 52,  sB + 16, sArow, smemHb, myrow);
    gcn_layer< 8, 16, false>(h, sW + 116, sB + 24, sArow, smemHb, myrow);
    gcn_layer<16, 16, false>(h, sW + 244, sB + 40, sArow, smemHb, myrow);
    gcn_layer<16, 32, true >(h, sW + 500, sB + 56, sArow, smemHb, myrow);
    __syncthreads();   // smemH now holds h768 per batch (flat index = node*32 + f)

    // ---- FC1: [32 x 768] @ [768 x 128], register-tiled 4b x 4o, packed f32x2 ----
    const int warp = t >> 5;
    const int lane = t & 31;
    const int b0 = warp * 4;     // warps 0..7 cover 32 batches
    const int o0 = lane * 4;     // lanes cover 128 outputs
    u64 a0[4], a1[4];
    #pragma unroll
    for (int i = 0; i < 4; i++){ a0[i] = 0ull; a1[i] = 0ull; }

    for (int c = 0; c < 12; c++){
        // stage fcw1 rows [c*64, c*64+64) x 128 -> 32KB tile, coalesced float4
        const float4* srcv = reinterpret_cast<const float4*>(fcw1) + c * 2048;
        float4* dstv = reinterpret_cast<float4*>(sWtile);
        for (int i = t; i < 2048; i += NT) dstv[i] = srcv[i];
        __syncthreads();
        if (warp < 8){
            const float* hc = smemH + b0 * 768 + c * 64;
            #pragma unroll 4
            for (int f2 = 0; f2 < 32; f2++){
                const float* wr = sWtile + (f2 * 2) * 128 + o0;
                V4 wa, wb;
                wa.q = *reinterpret_cast<const uint4*>(wr);         // row f
                wb.q = *reinterpret_cast<const uint4*>(wr + 128);   // row f+1
                #pragma unroll
                for (int bb = 0; bb < 4; bb++){
                    u64 hp = lds2(hc + bb * 768 + f2 * 2);          // broadcast
                    float hx, hy; upk2(hp, hx, hy);
                    u64 d0 = dup2(hx), d1 = dup2(hy);
                    a0[bb] = fma2(d0, wa.d[0], a0[bb]);
                    a1[bb] = fma2(d0, wa.d[1], a1[bb]);
                    a0[bb] = fma2(d1, wb.d[0], a0[bb]);
                    a1[bb] = fma2(d1, wb.d[1], a1[bb]);
                }
            }
        }
        __syncthreads();
    }

    // ---- write fc1 (+bias) into padded shared (stride 129: conflict-free) ----
    if (warp < 8){
        #pragma unroll
        for (int bb = 0; bb < 4; bb++){
            float v0, v1, v2, v3;
            upk2(a0[bb], v0, v1);
            upk2(a1[bb], v2, v3);
            float* dst = sfc1 + (b0 + bb) * 129 + o0;
            dst[0] = v0 + sFcb1[o0];
            dst[1] = v1 + sFcb1[o0 + 1];
            dst[2] = v2 + sFcb1[o0 + 2];
            dst[3] = v3 + sFcb1[o0 + 3];
        }
    }
    __syncthreads();

    // ---- FC2 + log_softmax (2 classes) ----
    if (t < 32){
        const float* r = sfc1 + t * 129;
        float z0 = sFcb2[0], z1 = sFcb2[1];
        #pragma unroll 8
        for (int o = 0; o < 128; o++){
            float v = r[o];
            z0 += v * sFcw2[2*o];
            z1 += v * sFcw2[2*o + 1];
        }
        float m = fmaxf(z0, z1);
        float lse = m + logf(expf(z0 - m) + expf(z1 - m));
        int gb = blockIdx.x * 32 + t;
        out[gb * 2 + 0] = z0 - lse;
        out[gb * 2 + 1] = z1 - lse;
    }
}

// ---------- launch ----------
extern "C" void kernel_launch(void* const* d_in, const int* in_sizes, int n_in,
                              void* d_out, int out_size)
{
    const float* x    = (const float*)d_in[0];
    const int*   ei   = (const int*)d_in[1];     // dtype-agnostic; decoded on device
    const float* W1   = (const float*)d_in[2];
    const float* b1   = (const float*)d_in[3];
    const float* W2   = (const float*)d_in[4];
    const float* b2   = (const float*)d_in[5];
    const float* W3   = (const float*)d_in[6];
    const float* b3   = (const float*)d_in[7];
    const float* W4   = (const float*)d_in[8];
    const float* b4   = (const float*)d_in[9];
    const float* W5   = (const float*)d_in[10];
    const float* b5   = (const float*)d_in[11];
    const float* W6   = (const float*)d_in[12];
    const float* b6   = (const float*)d_in[13];
    const float* W7   = (const float*)d_in[14];
    const float* b7   = (const float*)d_in[15];
    const float* fcw1 = (const float*)d_in[16];
    const float* fcb1 = (const float*)d_in[17];
    const float* fcw2 = (const float*)d_in[18];
    const float* fcb2 = (const float*)d_in[19];
    float* out = (float*)d_out;

    const int B = in_sizes[0] / 24;     // x has 24 elements per batch (F0=1)
    const int grid = B / TB;            // 32768/32 = 1024

    cudaFuncSetAttribute(gcn_fused_kernel,
                         cudaFuncAttributeMaxDynamicSharedMemorySize, SMEM_BYTES);

    build_adj_kernel<<<1, 576>>>(ei);
    gcn_fused_kernel<<<grid, NT, SMEM_BYTES>>>(x,
        W1, b1, W2, b2, W3, b3, W4, b4, W5, b5, W6, b6, W7, b7,
        fcw1, fcb1, fcw2, fcb2, out);
}

// round 4
// speedup vs baseline: 1.2917x; 1.2917x over previous
#include <cuda_runtime.h>
#include <math.h>

typedef unsigned long long u64;

__device__ __forceinline__ u64 dup2(float v){
    u64 r; asm("mov.b64 %0, {%1, %1};" : "=l"(r) : "f"(v)); return r;
}
__device__ __forceinline__ u64 pk2(float lo, float hi){
    u64 r; asm("mov.b64 %0, {%1, %2};" : "=l"(r) : "f"(lo), "f"(hi)); return r;
}
__device__ __forceinline__ void upk2(u64 a, float &lo, float &hi){
    asm("mov.b64 {%0, %1}, %2;" : "=f"(lo), "=f"(hi) : "l"(a));
}
__device__ __forceinline__ u64 fma2(u64 a, u64 b, u64 c){
    u64 d; asm("fma.rn.f32x2 %0, %1, %2, %3;" : "=l"(d) : "l"(a), "l"(b), "l"(c)); return d;
}
__device__ __forceinline__ u64 lds2(const float* p){ return *reinterpret_cast<const u64*>(p); }

union V4 { uint4 q; u64 d[2]; };

// ---------- adjacency prologue ----------
__device__ float g_adj[576];

__global__ void build_adj_kernel(const int* __restrict__ ei_raw){
    __shared__ float sdeg[24], sdinv[24], sAl[576];
    __shared__ int ssrc[96], sdst[96];
    __shared__ int is64;
    int t = threadIdx.x;
    if (t == 0){
        int z = 1;
        #pragma unroll 1
        for (int i = 1; i < 192; i += 2) if (ei_raw[i] != 0){ z = 0; break; }
        is64 = z;
    }
    if (t < 24) sdeg[t] = 1.0f;
    if (t < 576) sAl[t] = 0.0f;
    __syncthreads();
    if (t < 96){
        int s, d;
        if (is64){
            const long long* e = reinterpret_cast<const long long*>(ei_raw);
            s = (int)e[t]; d = (int)e[96 + t];
        } else { s = ei_raw[t]; d = ei_raw[96 + t]; }
        s = min(max(s,0),23); d = min(max(d,0),23);
        ssrc[t] = s; sdst[t] = d;
        atomicAdd(&sdeg[d], 1.0f);
    }
    __syncthreads();
    if (t < 24) sdinv[t] = 1.0f / sqrtf(sdeg[t]);
    __syncthreads();
    if (t < 96) atomicAdd(&sAl[sdst[t]*24 + ssrc[t]], sdinv[ssrc[t]]*sdinv[sdst[t]]);
    if (t < 24) atomicAdd(&sAl[t*24 + t], sdinv[t]*sdinv[t]);
    __syncthreads();
    if (t < 576) g_adj[t] = sAl[t];
}

// ---------- fused kernel ----------
#define NT 384
#define TB 16
#define RS 36                       // floats per node row
#define BSTR (24*RS)                // 864 floats per batch

constexpr int SM_H   = 0;           // 16*864 = 13824
constexpr int SM_WT  = 13824;       // 2*4096 = 8192 (double buffer; sfc1 overlay)
constexpr int SM_A   = 22016;       // 600
constexpr int SM_W   = 22616;       // 1012
constexpr int SM_B   = 23628;       // 88
constexpr int SM_FB1 = 23716;       // 128
constexpr int SM_FW2 = 23844;       // 256
constexpr int SM_FB2 = 24100;       // 2
constexpr int SMEM_FLOATS = 24102;
constexpr int SMEM_BYTES  = SMEM_FLOATS * 4;   // 96408

// in-place layer: g = A_row . H (FIN wide, registers), barrier, H_row = relu(g.W + b)
template<int FIN, int FOUT>
__device__ __forceinline__ void gcn_layer(float* Hb, float* myrow, const float* sArow,
                                          const float* sWl, const float* sBl)
{
    constexpr int GP = (FIN >= 2) ? FIN/2 : 1;
    u64 g[GP];
    float g0 = 0.f;
    if (FIN == 1){
        #pragma unroll 8
        for (int j = 0; j < 24; j++) g0 += sArow[j] * Hb[j*RS];
    } else {
        #pragma unroll
        for (int k = 0; k < GP; k++) g[k] = 0ull;
        #pragma unroll 4
        for (int j = 0; j < 24; j++){
            u64 a2 = dup2(sArow[j]);
            const float* row = Hb + j*RS;
            #pragma unroll
            for (int q = 0; q < FIN/4; q++){
                V4 v; v.q = *reinterpret_cast<const uint4*>(row + 4*q);
                g[2*q]   = fma2(a2, v.d[0], g[2*q]);
                g[2*q+1] = fma2(a2, v.d[1], g[2*q+1]);
            }
        }
    }
    __syncthreads();                 // reads done before in-place overwrite

    constexpr int KP = FOUT/2;
    u64 acc[KP];
    #pragma unroll
    for (int k = 0; k < KP; k++) acc[k] = lds2(sBl + 2*k);
    #pragma unroll
    for (int fi = 0; fi < FIN; fi++){
        float gs;
        if (FIN == 1) gs = g0;
        else { float lo, hi; upk2(g[fi/2], lo, hi); gs = (fi & 1) ? hi : lo; }
        u64 d = dup2(gs);
        #pragma unroll
        for (int k = 0; k < KP; k += 2){
            V4 wv; wv.q = *reinterpret_cast<const uint4*>(sWl + fi*FOUT + 2*k);
            acc[k]   = fma2(d, wv.d[0], acc[k]);
            acc[k+1] = fma2(d, wv.d[1], acc[k+1]);
        }
    }
    #pragma unroll
    for (int k = 0; k < KP; k += 2){
        float a,b,c,dd;
        upk2(acc[k], a, b); upk2(acc[k+1], c, dd);
        V4 o;
        o.d[0] = pk2(fmaxf(a,0.f), fmaxf(b,0.f));
        o.d[1] = pk2(fmaxf(c,0.f), fmaxf(dd,0.f));
        *reinterpret_cast<uint4*>(myrow + 2*k) = o.q;
    }
    __syncthreads();
}

__global__ __launch_bounds__(NT, 2)
void gcn_fused_kernel(const float* __restrict__ x,
                      const float* __restrict__ W1, const float* __restrict__ b1,
                      const float* __restrict__ W2, const float* __restrict__ b2,
                      const float* __restrict__ W3, const float* __restrict__ b3,
                      const float* __restrict__ W4, const float* __restrict__ b4,
                      const float* __restrict__ W5, const float* __restrict__ b5,
                      const float* __restrict__ W6, const float* __restrict__ b6,
                      const float* __restrict__ W7, const float* __restrict__ b7,
                      const float* __restrict__ fcw1, const float* __restrict__ fcb1,
                      const float* __restrict__ fcw2, const float* __restrict__ fcb2,
                      float* __restrict__ out)
{
    extern __shared__ float sm[];
    float* H    = sm + SM_H;
    float* Wt0  = sm + SM_WT;
    float* Wt1  = Wt0 + 4096;
    float* sfc1 = sm + SM_WT;        // overlay after FC1 loop finishes
    float* sA   = sm + SM_A;
    float* sW   = sm + SM_W;
    float* sB   = sm + SM_B;
    float* sFcb1= sm + SM_FB1;
    float* sFcw2= sm + SM_FW2;
    float* sFcb2= sm + SM_FB2;

    const int t = threadIdx.x;
    const int warp = t >> 5;
    const int lane = t & 31;

    // ---- stage constants (NT=384 aware) ----
    for (int i = t; i < 576; i += NT) sA[(i/24)*25 + (i%24)] = g_adj[i];
    if (t < 4)   sW[0   + t] = W1[t];
    if (t < 16)  sW[4   + t] = W2[t];
    if (t < 32)  sW[20  + t] = W3[t];
    if (t < 64)  sW[52  + t] = W4[t];
    if (t < 128) sW[116 + t] = W5[t];
    if (t < 256) sW[244 + t] = W6[t];
    for (int i = t; i < 512; i += NT) sW[500 + i] = W7[i];
    if (t < 4)   sB[0  + t] = b1[t];
    if (t < 4)   sB[4  + t] = b2[t];
    if (t < 8)   sB[8  + t] = b3[t];
    if (t < 8)   sB[16 + t] = b4[t];
    if (t < 16)  sB[24 + t] = b5[t];
    if (t < 16)  sB[40 + t] = b6[t];
    if (t < 32)  sB[56 + t] = b7[t];
    if (t < 128) sFcb1[t] = fcb1[t];
    if (t < 256) sFcw2[t] = fcw2[t];
    if (t < 2)   sFcb2[t] = fcb2[t];

    // ---- GCN phase: thread = (b_local = t/24, node = t%24) ----
    const int b_local = t / 24;
    const int node    = t % 24;
    float* Hb    = H + b_local * BSTR;
    float* myrow = Hb + node * RS;
    const float* sArow = sA + node * 25;

    myrow[0] = x[blockIdx.x * (TB*24) + t];   // [B,24,1] coalesced
    __syncthreads();

    gcn_layer< 1,  4>(Hb, myrow, sArow, sW + 0,   sB + 0 );
    gcn_layer< 4,  4>(Hb, myrow, sArow, sW + 4,   sB + 4 );
    gcn_layer< 4,  8>(Hb, myrow, sArow, sW + 20,  sB + 8 );
    gcn_layer< 8,  8>(Hb, myrow, sArow, sW + 52,  sB + 16);
    gcn_layer< 8, 16>(Hb, myrow, sArow, sW + 116, sB + 24);
    gcn_layer<16, 16>(Hb, myrow, sArow, sW + 244, sB + 40);
    gcn_layer<16, 32>(Hb, myrow, sArow, sW + 500, sB + 56);
    // H[b][node][0..31] = h768 (feature = node*32 + f)

    // ---- FC1: 24 chunks of 32 features (= node c), double-buffered W tile ----
    const float4* wsrc = reinterpret_cast<const float4*>(fcw1);
    for (int i = t; i < 1024; i += NT)
        reinterpret_cast<float4*>(Wt0)[i] = wsrc[i];
    __syncthreads();

    const int b0 = warp * 4;        // warps 0..3 compute 4 batches each
    const int o0 = lane * 4;
    u64 a0[4], a1[4];
    #pragma unroll
    for (int i = 0; i < 4; i++){ a0[i] = 0ull; a1[i] = 0ull; }

    for (int c = 0; c < 24; c++){
        const float* buf = (c & 1) ? Wt1 : Wt0;
        if (warp < 4){
            const float* hcb = H + b0 * BSTR + c * RS;
            #pragma unroll 4
            for (int f2 = 0; f2 < 16; f2++){
                const float* wr = buf + (2*f2) * 128 + o0;
                V4 wa, wb;
                wa.q = *reinterpret_cast<const uint4*>(wr);
                wb.q = *reinterpret_cast<const uint4*>(wr + 128);
                #pragma unroll
                for (int bb = 0; bb < 4; bb++){
                    u64 hp = lds2(hcb + bb * BSTR + 2*f2);
                    float hx, hy; upk2(hp, hx, hy);
                    u64 d0 = dup2(hx), d1 = dup2(hy);
                    a0[bb] = fma2(d0, wa.d[0], a0[bb]);
                    a1[bb] = fma2(d0, wa.d[1], a1[bb]);
                    a0[bb] = fma2(d1, wb.d[0], a0[bb]);
                    a1[bb] = fma2(d1, wb.d[1], a1[bb]);
                }
            }
        } else if (c + 1 < 24){
            float* nbuf = ((c+1) & 1) ? Wt1 : Wt0;
            const float4* src = wsrc + (c+1) * 1024;
            for (int i = t - 128; i < 1024; i += 256)
                reinterpret_cast<float4*>(nbuf)[i] = src[i];
        }
        __syncthreads();
    }

    // ---- fc1 + bias -> padded shared (stride 132) ----
    if (warp < 4){
        #pragma unroll
        for (int bb = 0; bb < 4; bb++){
            float v0,v1,v2,v3;
            upk2(a0[bb], v0, v1); upk2(a1[bb], v2, v3);
            float* dst = sfc1 + (b0 + bb) * 132 + o0;
            dst[0] = v0 + sFcb1[o0];
            dst[1] = v1 + sFcb1[o0+1];
            dst[2] = v2 + sFcb1[o0+2];
            dst[3] = v3 + sFcb1[o0+3];
        }
    }
    __syncthreads();

    // ---- FC2 + log_softmax ----
    if (t < TB){
        const float* r = sfc1 + t * 132;
        float z0 = sFcb2[0], z1 = sFcb2[1];
        #pragma unroll 8
        for (int o = 0; o < 128; o++){
            float v = r[o];
            z0 += v * sFcw2[2*o];
            z1 += v * sFcw2[2*o + 1];
        }
        float m = fmaxf(z0, z1);
        float lse = m + logf(expf(z0 - m) + expf(z1 - m));
        int gb = blockIdx.x * TB + t;
        out[gb*2 + 0] = z0 - lse;
        out[gb*2 + 1] = z1 - lse;
    }
}

extern "C" void kernel_launch(void* const* d_in, const int* in_sizes, int n_in,
                              void* d_out, int out_size)
{
    const float* x    = (const float*)d_in[0];
    const int*   ei   = (const int*)d_in[1];
    const float* W1   = (const float*)d_in[2];
    const float* b1   = (const float*)d_in[3];
    const float* W2   = (const float*)d_in[4];
    const float* b2   = (const float*)d_in[5];
    const float* W3   = (const float*)d_in[6];
    const float* b3   = (const float*)d_in[7];
    const float* W4   = (const float*)d_in[8];
    const float* b4   = (const float*)d_in[9];
    const float* W5   = (const float*)d_in[10];
    const float* b5   = (const float*)d_in[11];
    const float* W6   = (const float*)d_in[12];
    const float* b6   = (const float*)d_in[13];
    const float* W7   = (const float*)d_in[14];
    const float* b7   = (const float*)d_in[15];
    const float* fcw1 = (const float*)d_in[16];
    const float* fcb1 = (const float*)d_in[17];
    const float* fcw2 = (const float*)d_in[18];
    const float* fcb2 = (const float*)d_in[19];
    float* out = (float*)d_out;

    const int B = in_sizes[0] / 24;
    const int grid = B / TB;                    // 2048

    cudaFuncSetAttribute(gcn_fused_kernel,
                         cudaFuncAttributeMaxDynamicSharedMemorySize, SMEM_BYTES);

    build_adj_kernel<<<1, 576>>>(ei);
    gcn_fused_kernel<<<grid, NT, SMEM_BYTES>>>(x,
        W1, b1, W2, b2, W3, b3, W4, b4, W5, b5, W6, b6, W7, b7,
        fcw1, fcb1, fcw2, fcb2, out);
}

// round 5
// speedup vs baseline: 1.9657x; 1.5218x over previous
#include <cuda_runtime.h>
#include <math.h>

typedef unsigned long long u64;

__device__ __forceinline__ u64 dup2(float v){
    u64 r; asm("mov.b64 %0, {%1, %1};" : "=l"(r) : "f"(v)); return r;
}
__device__ __forceinline__ u64 pk2(float lo, float hi){
    u64 r; asm("mov.b64 %0, {%1, %2};" : "=l"(r) : "f"(lo), "f"(hi)); return r;
}
__device__ __forceinline__ void upk2(u64 a, float &lo, float &hi){
    asm("mov.b64 {%0, %1}, %2;" : "=f"(lo), "=f"(hi) : "l"(a));
}
__device__ __forceinline__ u64 fma2(u64 a, u64 b, u64 c){
    u64 d; asm("fma.rn.f32x2 %0, %1, %2, %3;" : "=l"(d) : "l"(a), "l"(b), "l"(c)); return d;
}
__device__ __forceinline__ u64 add2(u64 a, u64 b){
    u64 c; asm("add.rn.f32x2 %0, %1, %2;" : "=l"(c) : "l"(a), "l"(b)); return c;
}
__device__ __forceinline__ u64 lds2(const float* p){ return *reinterpret_cast<const u64*>(p); }

union V4 { uint4 q; u64 d[2]; };

// ---------- device globals ----------
__device__ float g_adj[576];
__device__ float g_wc[1540];   // Wc[768][2] then bc[2]

// ---------- adjacency prologue ----------
__global__ void build_adj_kernel(const int* __restrict__ ei_raw){
    __shared__ float sdeg[24], sdinv[24], sAl[576];
    __shared__ int ssrc[96], sdst[96];
    __shared__ int is64;
    int t = threadIdx.x;
    if (t == 0){
        int z = 1;
        #pragma unroll 1
        for (int i = 1; i < 192; i += 2) if (ei_raw[i] != 0){ z = 0; break; }
        is64 = z;
    }
    if (t < 24) sdeg[t] = 1.0f;
    if (t < 576) sAl[t] = 0.0f;
    __syncthreads();
    if (t < 96){
        int s, d;
        if (is64){
            const long long* e = reinterpret_cast<const long long*>(ei_raw);
            s = (int)e[t]; d = (int)e[96 + t];
        } else { s = ei_raw[t]; d = ei_raw[96 + t]; }
        s = min(max(s,0),23); d = min(max(d,0),23);
        ssrc[t] = s; sdst[t] = d;
        atomicAdd(&sdeg[d], 1.0f);
    }
    __syncthreads();
    if (t < 24) sdinv[t] = 1.0f / sqrtf(sdeg[t]);
    __syncthreads();
    if (t < 96) atomicAdd(&sAl[sdst[t]*24 + ssrc[t]], sdinv[ssrc[t]]*sdinv[sdst[t]]);
    if (t < 24) atomicAdd(&sAl[t*24 + t], sdinv[t]*sdinv[t]);
    __syncthreads();
    if (t < 576) g_adj[t] = sAl[t];
}

// ---------- fold fc head: Wc = fcw1 @ fcw2, bc = fcb1 @ fcw2 + fcb2 ----------
__global__ void build_wc_kernel(const float* __restrict__ fcw1, const float* __restrict__ fcb1,
                                const float* __restrict__ fcw2, const float* __restrict__ fcb2){
    __shared__ float sw2[256];
    int t = threadIdx.x;
    if (t < 256) sw2[t] = fcw2[t];
    __syncthreads();
    float a0 = 0.f, a1 = 0.f;
    const float* row = fcw1 + t * 128;
    #pragma unroll 8
    for (int k = 0; k < 128; k++){
        float w = row[k];
        a0 += w * sw2[2*k];
        a1 += w * sw2[2*k + 1];
    }
    g_wc[2*t]   = a0;
    g_wc[2*t+1] = a1;
    if (t < 2){
        float b = fcb2[t];
        #pragma unroll 8
        for (int k = 0; k < 128; k++) b += fcb1[k] * sw2[2*k + t];
        g_wc[1536 + t] = b;
    }
}

// ---------- fused GCN kernel ----------
#define NT 384
#define TB 16
#define RS 36
#define BSTR (24*RS)

constexpr int SM_H   = 0;        // 13824
constexpr int SM_WC  = 13824;    // 1540
constexpr int SM_A   = 15364;    // 600
constexpr int SM_W   = 15964;    // 1012
constexpr int SM_B   = 16976;    // 88
constexpr int SM_RED = 17064;    // 16*25 u64 = 800 floats
constexpr int SMEM_FLOATS = 17864;
constexpr int SMEM_BYTES  = SMEM_FLOATS * 4;    // 71456

template<int FIN, int FOUT>
__device__ __forceinline__ void gcn_layer(float* Hb, float* myrow, const float* sArow,
                                          const float* sWl, const float* sBl)
{
    constexpr int GP = (FIN >= 2) ? FIN/2 : 1;
    u64 g[GP];
    float g0 = 0.f;
    if (FIN == 1){
        #pragma unroll 8
        for (int j = 0; j < 24; j++) g0 += sArow[j] * Hb[j*RS];
    } else {
        #pragma unroll
        for (int k = 0; k < GP; k++) g[k] = 0ull;
        #pragma unroll 4
        for (int j = 0; j < 24; j++){
            u64 a2 = dup2(sArow[j]);
            const float* row = Hb + j*RS;
            #pragma unroll
            for (int q = 0; q < FIN/4; q++){
                V4 v; v.q = *reinterpret_cast<const uint4*>(row + 4*q);
                g[2*q]   = fma2(a2, v.d[0], g[2*q]);
                g[2*q+1] = fma2(a2, v.d[1], g[2*q+1]);
            }
        }
    }
    __syncthreads();

    constexpr int KP = FOUT/2;
    u64 acc[KP];
    #pragma unroll
    for (int k = 0; k < KP; k++) acc[k] = lds2(sBl + 2*k);
    #pragma unroll
    for (int fi = 0; fi < FIN; fi++){
        float gs;
        if (FIN == 1) gs = g0;
        else { float lo, hi; upk2(g[fi/2], lo, hi); gs = (fi & 1) ? hi : lo; }
        u64 d = dup2(gs);
        #pragma unroll
        for (int k = 0; k < KP; k += 2){
            V4 wv; wv.q = *reinterpret_cast<const uint4*>(sWl + fi*FOUT + 2*k);
            acc[k]   = fma2(d, wv.d[0], acc[k]);
            acc[k+1] = fma2(d, wv.d[1], acc[k+1]);
        }
    }
    #pragma unroll
    for (int k = 0; k < KP; k += 2){
        float a,b,c,dd;
        upk2(acc[k], a, b); upk2(acc[k+1], c, dd);
        V4 o;
        o.d[0] = pk2(fmaxf(a,0.f), fmaxf(b,0.f));
        o.d[1] = pk2(fmaxf(c,0.f), fmaxf(dd,0.f));
        *reinterpret_cast<uint4*>(myrow + 2*k) = o.q;
    }
    __syncthreads();
}

__global__ __launch_bounds__(NT, 3)
void gcn_fused_kernel(const float* __restrict__ x,
                      const float* __restrict__ W1, const float* __restrict__ b1,
                      const float* __restrict__ W2, const float* __restrict__ b2,
                      const float* __restrict__ W3, const float* __restrict__ b3,
                      const float* __restrict__ W4, const float* __restrict__ b4,
                      const float* __restrict__ W5, const float* __restrict__ b5,
                      const float* __restrict__ W6, const float* __restrict__ b6,
                      const float* __restrict__ W7, const float* __restrict__ b7,
                      float* __restrict__ out)
{
    extern __shared__ float sm[];
    float* H   = sm + SM_H;
    float* sWc = sm + SM_WC;
    float* sA  = sm + SM_A;
    float* sW  = sm + SM_W;
    float* sB  = sm + SM_B;
    float* sRed= sm + SM_RED;

    const int t = threadIdx.x;

    // ---- stage constants ----
    for (int i = t; i < 1540; i += NT) sWc[i] = g_wc[i];
    for (int i = t; i < 576; i += NT) sA[(i/24)*25 + (i%24)] = g_adj[i];
    if (t < 4)   sW[0   + t] = W1[t];
    if (t < 16)  sW[4   + t] = W2[t];
    if (t < 32)  sW[20  + t] = W3[t];
    if (t < 64)  sW[52  + t] = W4[t];
    if (t < 128) sW[116 + t] = W5[t];
    if (t < 256) sW[244 + t] = W6[t];
    for (int i = t; i < 512; i += NT) sW[500 + i] = W7[i];
    if (t < 4)   sB[0  + t] = b1[t];
    if (t < 4)   sB[4  + t] = b2[t];
    if (t < 8)   sB[8  + t] = b3[t];
    if (t < 8)   sB[16 + t] = b4[t];
    if (t < 16)  sB[24 + t] = b5[t];
    if (t < 16)  sB[40 + t] = b6[t];
    if (t < 32)  sB[56 + t] = b7[t];

    const int b_local = t / 24;
    const int node    = t % 24;
    float* Hb    = H + b_local * BSTR;
    float* myrow = Hb + node * RS;
    const float* sArow = sA + node * 25;

    myrow[0] = x[blockIdx.x * (TB*24) + t];
    __syncthreads();

    gcn_layer< 1,  4>(Hb, myrow, sArow, sW + 0,   sB + 0 );
    gcn_layer< 4,  4>(Hb, myrow, sArow, sW + 4,   sB + 4 );
    gcn_layer< 4,  8>(Hb, myrow, sArow, sW + 20,  sB + 8 );
    gcn_layer< 8,  8>(Hb, myrow, sArow, sW + 52,  sB + 16);
    gcn_layer< 8, 16>(Hb, myrow, sArow, sW + 116, sB + 24);
    gcn_layer<16, 16>(Hb, myrow, sArow, sW + 244, sB + 40);

    // ---- layer 7 fused with folded FC head ----
    // aggregate (FIN=16)
    u64 g[8];
    #pragma unroll
    for (int k = 0; k < 8; k++) g[k] = 0ull;
    #pragma unroll 4
    for (int j = 0; j < 24; j++){
        u64 a2 = dup2(sArow[j]);
        const float* row = Hb + j*RS;
        #pragma unroll
        for (int q = 0; q < 4; q++){
            V4 v; v.q = *reinterpret_cast<const uint4*>(row + 4*q);
            g[2*q]   = fma2(a2, v.d[0], g[2*q]);
            g[2*q+1] = fma2(a2, v.d[1], g[2*q+1]);
        }
    }
    // two passes of 16 outputs to cap registers; z = (z0,z1) partial for this node
    u64 z = 0ull;
    const float* wcn = sWc + node * 64;
    #pragma unroll
    for (int pass = 0; pass < 2; pass++){
        u64 acc[8];
        #pragma unroll
        for (int k = 0; k < 8; k++) acc[k] = lds2(sB + 56 + pass*16 + 2*k);
        #pragma unroll
        for (int fi = 0; fi < 16; fi++){
            float lo, hi; upk2(g[fi/2], lo, hi);
            u64 d = dup2((fi & 1) ? hi : lo);
            const float* wr = sW + 500 + fi*32 + pass*16;
            #pragma unroll
            for (int k = 0; k < 8; k += 2){
                V4 wv; wv.q = *reinterpret_cast<const uint4*>(wr + 2*k);
                acc[k]   = fma2(d, wv.d[0], acc[k]);
                acc[k+1] = fma2(d, wv.d[1], acc[k+1]);
            }
        }
        const float* wcp = wcn + pass * 32;
        #pragma unroll
        for (int k = 0; k < 8; k++){
            float a, b; upk2(acc[k], a, b);
            z = fma2(dup2(fmaxf(a, 0.f)), lds2(wcp + 4*k),     z);
            z = fma2(dup2(fmaxf(b, 0.f)), lds2(wcp + 4*k + 2), z);
        }
    }
    *reinterpret_cast<u64*>(sRed + (b_local*25 + node)*2) = z;
    __syncthreads();

    // ---- per-batch reduce + log_softmax ----
    if (t < TB){
        u64 s = lds2(sWc + 1536);   // bc
        const float* rb = sRed + t * 50;
        #pragma unroll 8
        for (int j = 0; j < 24; j++) s = add2(s, lds2(rb + 2*j));
        float z0, z1; upk2(s, z0, z1);
        float m = fmaxf(z0, z1);
        float lse = m + logf(expf(z0 - m) + expf(z1 - m));
        int gb = blockIdx.x * TB + t;
        out[gb*2 + 0] = z0 - lse;
        out[gb*2 + 1] = z1 - lse;
    }
}

extern "C" void kernel_launch(void* const* d_in, const int* in_sizes, int n_in,
                              void* d_out, int out_size)
{
    const float* x    = (const float*)d_in[0];
    const int*   ei   = (const int*)d_in[1];
    const float* W1   = (const float*)d_in[2];
    const float* b1   = (const float*)d_in[3];
    const float* W2   = (const float*)d_in[4];
    const float* b2   = (const float*)d_in[5];
    const float* W3   = (const float*)d_in[6];
    const float* b3   = (const float*)d_in[7];
    const float* W4   = (const float*)d_in[8];
    const float* b4   = (const float*)d_in[9];
    const float* W5   = (const float*)d_in[10];
    const float* b5   = (const float*)d_in[11];
    const float* W6   = (const float*)d_in[12];
    const float* b6   = (const float*)d_in[13];
    const float* W7   = (const float*)d_in[14];
    const float* b7   = (const float*)d_in[15];
    const float* fcw1 = (const float*)d_in[16];
    const float* fcb1 = (const float*)d_in[17];
    const float* fcw2 = (const float*)d_in[18];
    const float* fcb2 = (const float*)d_in[19];
    float* out = (float*)d_out;

    const int B = in_sizes[0] / 24;
    const int grid = B / TB;

    cudaFuncSetAttribute(gcn_fused_kernel,
                         cudaFuncAttributeMaxDynamicSharedMemorySize, SMEM_BYTES);

    build_adj_kernel<<<1, 576>>>(ei);
    build_wc_kernel<<<1, 768>>>(fcw1, fcb1, fcw2, fcb2);
    gcn_fused_kernel<<<grid, NT, SMEM_BYTES>>>(x,
        W1, b1, W2, b2, W3, b3, W4, b4, W5, b5, W6, b6, W7, b7, out);
}

// round 6
// speedup vs baseline: 2.2171x; 1.1279x over previous
#include <cuda_runtime.h>
#include <math.h>

typedef unsigned long long u64;

__device__ __forceinline__ u64 dup2(float v){
    u64 r; asm("mov.b64 %0, {%1, %1};" : "=l"(r) : "f"(v)); return r;
}
__device__ __forceinline__ u64 pk2(float lo, float hi){
    u64 r; asm("mov.b64 %0, {%1, %2};" : "=l"(r) : "f"(lo), "f"(hi)); return r;
}
__device__ __forceinline__ void upk2(u64 a, float &lo, float &hi){
    asm("mov.b64 {%0, %1}, %2;" : "=f"(lo), "=f"(hi) : "l"(a));
}
__device__ __forceinline__ u64 fma2(u64 a, u64 b, u64 c){
    u64 d; asm("fma.rn.f32x2 %0, %1, %2, %3;" : "=l"(d) : "l"(a), "l"(b), "l"(c)); return d;
}
__device__ __forceinline__ u64 add2(u64 a, u64 b){
    u64 c; asm("add.rn.f32x2 %0, %1, %2;" : "=l"(c) : "l"(a), "l"(b)); return c;
}
__device__ __forceinline__ u64 lds2(const float* p){ return *reinterpret_cast<const u64*>(p); }

union V4 { uint4 q; u64 d[2]; };

// ---------- constant memory: warp-uniform operands ----------
__constant__ float c_W[1012];   // W1..W7 packed at offsets 0,4,20,52,116,244,500
__constant__ float c_B[88];     // b1..b7 packed at offsets 0,4,8,16,24,40,56

// ---------- device globals ----------
__device__ float g_adj[576];
__device__ float g_wc[1540];    // Wc[768][2] then bc[2]

// ---------- adjacency prologue ----------
__global__ void build_adj_kernel(const int* __restrict__ ei_raw){
    __shared__ float sdeg[24], sdinv[24], sAl[576];
    __shared__ int ssrc[96], sdst[96];
    __shared__ int is64;
    int t = threadIdx.x;
    if (t == 0){
        int z = 1;
        #pragma unroll 1
        for (int i = 1; i < 192; i += 2) if (ei_raw[i] != 0){ z = 0; break; }
        is64 = z;
    }
    if (t < 24) sdeg[t] = 1.0f;
    if (t < 576) sAl[t] = 0.0f;
    __syncthreads();
    if (t < 96){
        int s, d;
        if (is64){
            const long long* e = reinterpret_cast<const long long*>(ei_raw);
            s = (int)e[t]; d = (int)e[96 + t];
        } else { s = ei_raw[t]; d = ei_raw[96 + t]; }
        s = min(max(s,0),23); d = min(max(d,0),23);
        ssrc[t] = s; sdst[t] = d;
        atomicAdd(&sdeg[d], 1.0f);
    }
    __syncthreads();
    if (t < 24) sdinv[t] = 1.0f / sqrtf(sdeg[t]);
    __syncthreads();
    if (t < 96) atomicAdd(&sAl[sdst[t]*24 + ssrc[t]], sdinv[ssrc[t]]*sdinv[sdst[t]]);
    if (t < 24) atomicAdd(&sAl[t*24 + t], sdinv[t]*sdinv[t]);
    __syncthreads();
    if (t < 576) g_adj[t] = sAl[t];
}

// ---------- fold fc head: Wc = fcw1 @ fcw2, bc = fcb1 @ fcw2 + fcb2 ----------
__global__ void build_wc_kernel(const float* __restrict__ fcw1, const float* __restrict__ fcb1,
                                const float* __restrict__ fcw2, const float* __restrict__ fcb2){
    __shared__ float sw2[256];
    int t = threadIdx.x;
    if (t < 256) sw2[t] = fcw2[t];
    __syncthreads();
    float a0 = 0.f, a1 = 0.f;
    const float* row = fcw1 + t * 128;
    #pragma unroll 8
    for (int k = 0; k < 128; k++){
        float w = row[k];
        a0 += w * sw2[2*k];
        a1 += w * sw2[2*k + 1];
    }
    g_wc[2*t]   = a0;
    g_wc[2*t+1] = a1;
    if (t < 2){
        float b = fcb2[t];
        #pragma unroll 8
        for (int k = 0; k < 128; k++) b += fcb1[k] * sw2[2*k + t];
        g_wc[1536 + t] = b;
    }
}

// ---------- fused GCN kernel ----------
#define NT 384
#define TB 16
#define RS 36
#define BSTR (24*RS)

constexpr int SM_H   = 0;        // 13824
constexpr int SM_WC  = 13824;    // 1540
constexpr int SM_A   = 15364;    // 600
constexpr int SM_RED = 15964;    // 16*25 u64 = 800 floats
constexpr int SMEM_FLOATS = 16764;
constexpr int SMEM_BYTES  = SMEM_FLOATS * 4;   // 67056 -> 3 blocks/SM

template<int FIN, int FOUT, int WOFF, int BOFF>
__device__ __forceinline__ void gcn_layer(float* Hb, float* myrow, const float* sArow)
{
    constexpr int GP = (FIN >= 2) ? FIN/2 : 1;
    u64 g[GP];
    float g0 = 0.f;
    if (FIN == 1){
        #pragma unroll 8
        for (int j = 0; j < 24; j++) g0 += sArow[j] * Hb[j*RS];
    } else {
        #pragma unroll
        for (int k = 0; k < GP; k++) g[k] = 0ull;
        #pragma unroll 4
        for (int j = 0; j < 24; j++){
            u64 a2 = dup2(sArow[j]);
            const float* row = Hb + j*RS;
            #pragma unroll
            for (int q = 0; q < FIN/4; q++){
                V4 v; v.q = *reinterpret_cast<const uint4*>(row + 4*q);
                g[2*q]   = fma2(a2, v.d[0], g[2*q]);
                g[2*q+1] = fma2(a2, v.d[1], g[2*q+1]);
            }
        }
    }
    __syncthreads();

    constexpr int KP = FOUT/2;
    u64 acc[KP];
    #pragma unroll
    for (int k = 0; k < KP; k++) acc[k] = pk2(c_B[BOFF + 2*k], c_B[BOFF + 2*k + 1]);
    #pragma unroll
    for (int fi = 0; fi < FIN; fi++){
        float gs;
        if (FIN == 1) gs = g0;
        else { float lo, hi; upk2(g[fi/2], lo, hi); gs = (fi & 1) ? hi : lo; }
        u64 d = dup2(gs);
        #pragma unroll
        for (int k = 0; k < KP; k++){
            u64 w = pk2(c_W[WOFF + fi*FOUT + 2*k], c_W[WOFF + fi*FOUT + 2*k + 1]);
            acc[k] = fma2(d, w, acc[k]);
        }
    }
    #pragma unroll
    for (int k = 0; k < KP; k += 2){
        float a,b,c,dd;
        upk2(acc[k], a, b); upk2(acc[k+1], c, dd);
        V4 o;
        o.d[0] = pk2(fmaxf(a,0.f), fmaxf(b,0.f));
        o.d[1] = pk2(fmaxf(c,0.f), fmaxf(dd,0.f));
        *reinterpret_cast<uint4*>(myrow + 2*k) = o.q;
    }
    __syncthreads();
}

__global__ __launch_bounds__(NT, 3)
void gcn_fused_kernel(const float* __restrict__ x, float* __restrict__ out)
{
    extern __shared__ float sm[];
    float* H   = sm + SM_H;
    float* sWc = sm + SM_WC;
    float* sA  = sm + SM_A;
    float* sRed= sm + SM_RED;

    const int t = threadIdx.x;

    for (int i = t; i < 1540; i += NT) sWc[i] = g_wc[i];
    for (int i = t; i < 576; i += NT) sA[(i/24)*25 + (i%24)] = g_adj[i];

    const int b_local = t / 24;
    const int node    = t % 24;
    float* Hb    = H + b_local * BSTR;
    float* myrow = Hb + node * RS;
    const float* sArow = sA + node * 25;

    myrow[0] = x[blockIdx.x * (TB*24) + t];
    __syncthreads();

    gcn_layer< 1,  4,   0,  0>(Hb, myrow, sArow);
    gcn_layer< 4,  4,   4,  4>(Hb, myrow, sArow);
    gcn_layer< 4,  8,  20,  8>(Hb, myrow, sArow);
    gcn_layer< 8,  8,  52, 16>(Hb, myrow, sArow);
    gcn_layer< 8, 16, 116, 24>(Hb, myrow, sArow);
    gcn_layer<16, 16, 244, 40>(Hb, myrow, sArow);

    // ---- layer 7 (16->32) fused with folded FC head ----
    u64 g[8];
    #pragma unroll
    for (int k = 0; k < 8; k++) g[k] = 0ull;
    #pragma unroll 4
    for (int j = 0; j < 24; j++){
        u64 a2 = dup2(sArow[j]);
        const float* row = Hb + j*RS;
        #pragma unroll
        for (int q = 0; q < 4; q++){
            V4 v; v.q = *reinterpret_cast<const uint4*>(row + 4*q);
            g[2*q]   = fma2(a2, v.d[0], g[2*q]);
            g[2*q+1] = fma2(a2, v.d[1], g[2*q+1]);
        }
    }
    u64 z = 0ull;
    const float* wcn = sWc + node * 64;
    #pragma unroll
    for (int pass = 0; pass < 2; pass++){
        u64 acc[8];
        #pragma unroll
        for (int k = 0; k < 8; k++)
            acc[k] = pk2(c_B[56 + pass*16 + 2*k], c_B[56 + pass*16 + 2*k + 1]);
        #pragma unroll
        for (int fi = 0; fi < 16; fi++){
            float lo, hi; upk2(g[fi/2], lo, hi);
            u64 d = dup2((fi & 1) ? hi : lo);
            #pragma unroll
            for (int k = 0; k < 8; k++){
                u64 w = pk2(c_W[500 + fi*32 + pass*16 + 2*k],
                            c_W[500 + fi*32 + pass*16 + 2*k + 1]);
                acc[k] = fma2(d, w, acc[k]);
            }
        }
        const float* wcp = wcn + pass * 32;
        #pragma unroll
        for (int k = 0; k < 8; k++){
            float a, b; upk2(acc[k], a, b);
            z = fma2(dup2(fmaxf(a, 0.f)), lds2(wcp + 4*k),     z);
            z = fma2(dup2(fmaxf(b, 0.f)), lds2(wcp + 4*k + 2), z);
        }
    }
    *reinterpret_cast<u64*>(sRed + (b_local*25 + node)*2) = z;
    __syncthreads();

    if (t < TB){
        u64 s = lds2(sWc + 1536);   // bc
        const float* rb = sRed + t * 50;
        #pragma unroll 8
        for (int j = 0; j < 24; j++) s = add2(s, lds2(rb + 2*j));
        float z0, z1; upk2(s, z0, z1);
        float m = fmaxf(z0, z1);
        float lse = m + logf(expf(z0 - m) + expf(z1 - m));
        int gb = blockIdx.x * TB + t;
        out[gb*2 + 0] = z0 - lse;
        out[gb*2 + 1] = z1 - lse;
    }
}

extern "C" void kernel_launch(void* const* d_in, const int* in_sizes, int n_in,
                              void* d_out, int out_size)
{
    const float* x    = (const float*)d_in[0];
    const int*   ei   = (const int*)d_in[1];
    const float* fcw1 = (const float*)d_in[16];
    const float* fcb1 = (const float*)d_in[17];
    const float* fcw2 = (const float*)d_in[18];
    const float* fcb2 = (const float*)d_in[19];
    float* out = (float*)d_out;

    // ---- stage W/b into constant memory (DtoD memcpys, graph-capturable) ----
    static const int woff[7] = {0, 4, 20, 52, 116, 244, 500};
    static const int wsz [7] = {4, 16, 32, 64, 128, 256, 512};
    static const int boff[7] = {0, 4, 8, 16, 24, 40, 56};
    static const int bsz [7] = {4, 4, 8, 8, 16, 16, 32};
    for (int i = 0; i < 7; i++){
        cudaMemcpyToSymbolAsync(c_W, d_in[2 + 2*i], wsz[i]*4, woff[i]*4,
                                cudaMemcpyDeviceToDevice, 0);
        cudaMemcpyToSymbolAsync(c_B, d_in[3 + 2*i], bsz[i]*4, boff[i]*4,
                                cudaMemcpyDeviceToDevice, 0);
    }

    const int B = in_sizes[0] / 24;
    const int grid = B / TB;

    cudaFuncSetAttribute(gcn_fused_kernel,
                         cudaFuncAttributeMaxDynamicSharedMemorySize, SMEM_BYTES);

    build_adj_kernel<<<1, 576>>>(ei);
    build_wc_kernel<<<1, 768>>>(fcw1, fcb1, fcw2, fcb2);
    gcn_fused_kernel<<<grid, NT, SMEM_BYTES>>>(x, out);
}

// round 7
// speedup vs baseline: 2.5703x; 1.1593x over previous
#include <cuda_runtime.h>
#include <math.h>

typedef unsigned long long u64;

__device__ __forceinline__ u64 dup2(float v){
    u64 r; asm("mov.b64 %0, {%1, %1};" : "=l"(r) : "f"(v)); return r;
}
__device__ __forceinline__ u64 pk2(float lo, float hi){
    u64 r; asm("mov.b64 %0, {%1, %2};" : "=l"(r) : "f"(lo), "f"(hi)); return r;
}
__device__ __forceinline__ void upk2(u64 a, float &lo, float &hi){
    asm("mov.b64 {%0, %1}, %2;" : "=f"(lo), "=f"(hi) : "l"(a));
}
__device__ __forceinline__ u64 fma2(u64 a, u64 b, u64 c){
    u64 d; asm("fma.rn.f32x2 %0, %1, %2, %3;" : "=l"(d) : "l"(a), "l"(b), "l"(c)); return d;
}
__device__ __forceinline__ u64 add2(u64 a, u64 b){
    u64 c; asm("add.rn.f32x2 %0, %1, %2;" : "=l"(c) : "l"(a), "l"(b)); return c;
}
__device__ __forceinline__ u64 lds2(const float* p){ return *reinterpret_cast<const u64*>(p); }

union V4 { uint4 q; u64 d[2]; };

// ---------- constant memory: warp-uniform operands ----------
__constant__ float c_W[1012];   // W1..W7 at offsets 0,4,20,52,116,244,500
__constant__ float c_B[88];     // b1..b7 at offsets 0,4,8,16,24,40,56

// ---------- device globals ----------
__device__ float g_adj[576];
__device__ float g_wc[1586];    // Wc padded: node stride 66 (24*66), bc at [1584..1585]

// ---------- adjacency prologue ----------
__global__ void build_adj_kernel(const int* __restrict__ ei_raw){
    __shared__ float sdeg[24], sdinv[24], sAl[576];
    __shared__ int ssrc[96], sdst[96];
    __shared__ int is64;
    int t = threadIdx.x;
    if (t == 0){
        int z = 1;
        #pragma unroll 1
        for (int i = 1; i < 192; i += 2) if (ei_raw[i] != 0){ z = 0; break; }
        is64 = z;
    }
    if (t < 24) sdeg[t] = 1.0f;
    if (t < 576) sAl[t] = 0.0f;
    __syncthreads();
    if (t < 96){
        int s, d;
        if (is64){
            const long long* e = reinterpret_cast<const long long*>(ei_raw);
            s = (int)e[t]; d = (int)e[96 + t];
        } else { s = ei_raw[t]; d = ei_raw[96 + t]; }
        s = min(max(s,0),23); d = min(max(d,0),23);
        ssrc[t] = s; sdst[t] = d;
        atomicAdd(&sdeg[d], 1.0f);
    }
    __syncthreads();
    if (t < 24) sdinv[t] = 1.0f / sqrtf(sdeg[t]);
    __syncthreads();
    if (t < 96) atomicAdd(&sAl[sdst[t]*24 + ssrc[t]], sdinv[ssrc[t]]*sdinv[sdst[t]]);
    if (t < 24) atomicAdd(&sAl[t*24 + t], sdinv[t]*sdinv[t]);
    __syncthreads();
    if (t < 576) g_adj[t] = sAl[t];
}

// ---------- fold fc head: Wc = fcw1 @ fcw2 (padded layout), bc = fcb1 @ fcw2 + fcb2 ----------
__global__ void build_wc_kernel(const float* __restrict__ fcw1, const float* __restrict__ fcb1,
                                const float* __restrict__ fcw2, const float* __restrict__ fcb2){
    __shared__ float sw2[256];
    int t = threadIdx.x;        // t = f = node*32 + fi
    if (t < 256) sw2[t] = fcw2[t];
    __syncthreads();
    float a0 = 0.f, a1 = 0.f;
    const float* row = fcw1 + t * 128;
    #pragma unroll 8
    for (int k = 0; k < 128; k++){
        float w = row[k];
        a0 += w * sw2[2*k];
        a1 += w * sw2[2*k + 1];
    }
    int node = t >> 5, fi = t & 31;
    g_wc[node*66 + 2*fi]     = a0;
    g_wc[node*66 + 2*fi + 1] = a1;
    if (t < 2){
        float b = fcb2[t];
        #pragma unroll 8
        for (int k = 0; k < 128; k++) b += fcb1[k] * sw2[2*k + t];
        g_wc[1584 + t] = b;
    }
}

// ---------- fused GCN kernel ----------
#define NT 384
#define TB 16
#define RS2 20                    // ping-pong row stride (max 16 feats + pad)
#define BST2 (24*RS2)             // 480 floats per batch

constexpr int SM_BA  = 0;         // bufA: 16*480 = 7680
constexpr int SM_BB  = 7680;      // bufB: 7680
constexpr int SM_WC  = 15360;     // 1586
constexpr int SM_A   = 16948;     // 600 (16B aligned)
constexpr int SM_RED = 17548;     // 16*25*2 = 800
constexpr int SMEM_FLOATS = 18348;
constexpr int SMEM_BYTES  = SMEM_FLOATS * 4;   // 73392 -> 3 blocks/SM

// ping-pong layer: g = A_row . bufIn (no pre-sync), out = relu(g.W+b) -> bufOut, sync
template<int FIN, int FOUT, int WOFF, int BOFF>
__device__ __forceinline__ void gcn_layer(const float* bIn, float* outRow, const float* sArow)
{
    constexpr int GP = (FIN >= 2) ? FIN/2 : 1;
    u64 g[GP];
    float g0 = 0.f;
    if (FIN == 1){
        #pragma unroll 8
        for (int j = 0; j < 24; j++) g0 += sArow[j] * bIn[j*RS2];
    } else {
        #pragma unroll
        for (int k = 0; k < GP; k++) g[k] = 0ull;
        #pragma unroll 4
        for (int j = 0; j < 24; j++){
            u64 a2 = dup2(sArow[j]);
            const float* row = bIn + j*RS2;
            #pragma unroll
            for (int q = 0; q < FIN/4; q++){
                V4 v; v.q = *reinterpret_cast<const uint4*>(row + 4*q);
                g[2*q]   = fma2(a2, v.d[0], g[2*q]);
                g[2*q+1] = fma2(a2, v.d[1], g[2*q+1]);
            }
        }
    }

    constexpr int KP = FOUT/2;
    u64 acc[KP];
    #pragma unroll
    for (int k = 0; k < KP; k++) acc[k] = pk2(c_B[BOFF + 2*k], c_B[BOFF + 2*k + 1]);
    #pragma unroll
    for (int fi = 0; fi < FIN; fi++){
        float gs;
        if (FIN == 1) gs = g0;
        else { float lo, hi; upk2(g[fi/2], lo, hi); gs = (fi & 1) ? hi : lo; }
        u64 d = dup2(gs);
        #pragma unroll
        for (int k = 0; k < KP; k++){
            u64 w = pk2(c_W[WOFF + fi*FOUT + 2*k], c_W[WOFF + fi*FOUT + 2*k + 1]);
            acc[k] = fma2(d, w, acc[k]);
        }
    }
    #pragma unroll
    for (int k = 0; k < KP; k += 2){
        float a,b,c,dd;
        upk2(acc[k], a, b); upk2(acc[k+1], c, dd);
        V4 o;
        o.d[0] = pk2(fmaxf(a,0.f), fmaxf(b,0.f));
        o.d[1] = pk2(fmaxf(c,0.f), fmaxf(dd,0.f));
        *reinterpret_cast<uint4*>(outRow + 2*k) = o.q;
    }
    __syncthreads();
}

__global__ __launch_bounds__(NT, 3)
void gcn_fused_kernel(const float* __restrict__ x, float* __restrict__ out)
{
    extern __shared__ float sm[];
    float* bufA = sm + SM_BA;
    float* bufB = sm + SM_BB;
    float* sWc  = sm + SM_WC;
    float* sA   = sm + SM_A;
    float* sRed = sm + SM_RED;

    const int t = threadIdx.x;

    for (int i = t; i < 1586; i += NT) sWc[i] = g_wc[i];
    for (int i = t; i < 576; i += NT) sA[(i/24)*25 + (i%24)] = g_adj[i];

    const int b_local = t / 24;
    const int node    = t % 24;
    const float* inA = bufA + b_local * BST2;
    const float* inB = bufB + b_local * BST2;
    float* rowA = bufA + b_local * BST2 + node * RS2;
    float* rowB = bufB + b_local * BST2 + node * RS2;
    const float* sArow = sA + node * 25;

    rowA[0] = x[blockIdx.x * (TB*24) + t];
    __syncthreads();

    gcn_layer< 1,  4,   0,  0>(inA, rowB, sArow);
    gcn_layer< 4,  4,   4,  4>(inB, rowA, sArow);
    gcn_layer< 4,  8,  20,  8>(inA, rowB, sArow);
    gcn_layer< 8,  8,  52, 16>(inB, rowA, sArow);
    gcn_layer< 8, 16, 116, 24>(inA, rowB, sArow);
    gcn_layer<16, 16, 244, 40>(inB, rowA, sArow);

    // ---- layer 7 (16->32) fused with folded FC head (reads bufA, regs only) ----
    u64 g[8];
    #pragma unroll
    for (int k = 0; k < 8; k++) g[k] = 0ull;
    #pragma unroll 4
    for (int j = 0; j < 24; j++){
        u64 a2 = dup2(sArow[j]);
        const float* row = inA + j*RS2;
        #pragma unroll
        for (int q = 0; q < 4; q++){
            V4 v; v.q = *reinterpret_cast<const uint4*>(row + 4*q);
            g[2*q]   = fma2(a2, v.d[0], g[2*q]);
            g[2*q+1] = fma2(a2, v.d[1], g[2*q+1]);
        }
    }
    u64 z = 0ull;
    const float* wcn = sWc + node * 66;     // padded: no bank conflicts
    #pragma unroll
    for (int pass = 0; pass < 2; pass++){
        u64 acc[8];
        #pragma unroll
        for (int k = 0; k < 8; k++)
            acc[k] = pk2(c_B[56 + pass*16 + 2*k], c_B[56 + pass*16 + 2*k + 1]);
        #pragma unroll
        for (int fi = 0; fi < 16; fi++){
            float lo, hi; upk2(g[fi/2], lo, hi);
            u64 d = dup2((fi & 1) ? hi : lo);
            #pragma unroll
            for (int k = 0; k < 8; k++){
                u64 w = pk2(c_W[500 + fi*32 + pass*16 + 2*k],
                            c_W[500 + fi*32 + pass*16 + 2*k + 1]);
                acc[k] = fma2(d, w, acc[k]);
            }
        }
        const float* wcp = wcn + pass * 32;
        #pragma unroll
        for (int k = 0; k < 8; k++){
            float a, b; upk2(acc[k], a, b);
            z = fma2(dup2(fmaxf(a, 0.f)), lds2(wcp + 4*k),     z);
            z = fma2(dup2(fmaxf(b, 0.f)), lds2(wcp + 4*k + 2), z);
        }
    }
    *reinterpret_cast<u64*>(sRed + (b_local*25 + node)*2) = z;
    __syncthreads();

    if (t < TB){
        u64 s = lds2(sWc + 1584);   // bc
        const float* rb = sRed + t * 50;
        #pragma unroll 8
        for (int j = 0; j < 24; j++) s = add2(s, lds2(rb + 2*j));
        float z0, z1; upk2(s, z0, z1);
        float m = fmaxf(z0, z1);
        float lse = m + logf(expf(z0 - m) + expf(z1 - m));
        int gb = blockIdx.x * TB + t;
        out[gb*2 + 0] = z0 - lse;
        out[gb*2 + 1] = z1 - lse;
    }
}

extern "C" void kernel_launch(void* const* d_in, const int* in_sizes, int n_in,
                              void* d_out, int out_size)
{
    const float* x    = (const float*)d_in[0];
    const int*   ei   = (const int*)d_in[1];
    const float* fcw1 = (const float*)d_in[16];
    const float* fcb1 = (const float*)d_in[17];
    const float* fcw2 = (const float*)d_in[18];
    const float* fcb2 = (const float*)d_in[19];
    float* out = (float*)d_out;

    static const int woff[7] = {0, 4, 20, 52, 116, 244, 500};
    static const int wsz [7] = {4, 16, 32, 64, 128, 256, 512};
    static const int boff[7] = {0, 4, 8, 16, 24, 40, 56};
    static const int bsz [7] = {4, 4, 8, 8, 16, 16, 32};
    for (int i = 0; i < 7; i++){
        cudaMemcpyToSymbolAsync(c_W, d_in[2 + 2*i], wsz[i]*4, woff[i]*4,
                                cudaMemcpyDeviceToDevice, 0);
        cudaMemcpyToSymbolAsync(c_B, d_in[3 + 2*i], bsz[i]*4, boff[i]*4,
                                cudaMemcpyDeviceToDevice, 0);
    }

    const int B = in_sizes[0] / 24;
    const int grid = B / TB;

    cudaFuncSetAttribute(gcn_fused_kernel,
                         cudaFuncAttributeMaxDynamicSharedMemorySize, SMEM_BYTES);

    build_adj_kernel<<<1, 576>>>(ei);
    build_wc_kernel<<<1, 768>>>(fcw1, fcb1, fcw2, fcb2);
    gcn_fused_kernel<<<grid, NT, SMEM_BYTES>>>(x, out);
}